// round 5
// baseline (speedup 1.0000x reference)
#include <cuda_runtime.h>
#include <cuda_bf16.h>
#include <cstdint>

// Problem constants
#define B_SZ   16
#define CIN    512
#define L_IN   4000
#define KW     16
#define STRIDE 8
#define L_OUT  31992            // (4000-1)*8 - 16 + 16
#define CSPLIT 2
#define CHALF  (CIN / CSPLIT)   // 256
#define MP     4                // m-values per thread

// Intermediate z[half][b][m][k] = sum_{cin in half} x[b,cin,m] * W_b[cin,k]
__device__ float g_zbuf[CSPLIT * B_SZ * L_IN * KW];   // 8.2 MB scratch

// ---------------------------------------------------------------------------
// Kernel 1: per-sample skinny GEMM  z = x^T @ W_b, f32x2 packed over K-PAIRS.
// W stays in natural layout in smem (16 KB, no duplication): per cin a thread
// does 4 LDS.128 (64 B of W) + 1 LDG.128 (4 m-values of x) + 32 FFMA2
// -> 1 B of smem crossbar per MAC (4x less than round 4's layout).
// Grid: (4 m-tiles of 1024, 16 batch, 2 cin-halves) x 256 thr = 128 blocks.
// ---------------------------------------------------------------------------
extern "C" __global__ void __launch_bounds__(256)
zgemm_kernel(const float* __restrict__ x,
             const float* __restrict__ t60s,
             const float* __restrict__ kw)
{
    __shared__ __align__(16) float Wsm[CHALF * KW];   // natural layout, 16 KB

    const int b    = blockIdx.y;
    const int half = blockIdx.z;
    // idx = round(t60*100) - 10, tiled so b>=8 reuses t60s[b-8]
    const int idxb = (int)rintf(t60s[b & 7] * 100.0f) - 10;
    const float4* wsrc = (const float4*)(kw + (size_t)idxb * (CIN * KW)
                                            + half * (CHALF * KW));
    float4* wdst = (float4*)Wsm;
    for (int i = threadIdx.x; i < CHALF * KW / 4; i += 256)
        wdst[i] = wsrc[i];
    __syncthreads();

    const int m = blockIdx.x * (256 * MP) + threadIdx.x * MP;
    if (m >= L_IN) return;   // last-tile guard (after the only __syncthreads)

    const float* xp = x + (size_t)b * CIN * L_IN + (size_t)half * CHALF * L_IN + m;
    const ulonglong2* Wp = (const ulonglong2*)Wsm;    // 4 x LDS.128 per cin row

    unsigned long long acc[MP][8];                    // [m][k-pair], {k_lo,k_hi}
#pragma unroll
    for (int mi = 0; mi < MP; ++mi)
#pragma unroll
        for (int j = 0; j < 8; ++j) acc[mi][j] = 0ULL;

#pragma unroll 8
    for (int cin = 0; cin < CHALF; ++cin) {
        float4 xq = *(const float4*)(xp + (size_t)cin * L_IN);   // m..m+3
        unsigned long long xv[MP];
        asm("mov.b64 %0, {%1, %1};" : "=l"(xv[0]) : "f"(xq.x));
        asm("mov.b64 %0, {%1, %1};" : "=l"(xv[1]) : "f"(xq.y));
        asm("mov.b64 %0, {%1, %1};" : "=l"(xv[2]) : "f"(xq.z));
        asm("mov.b64 %0, {%1, %1};" : "=l"(xv[3]) : "f"(xq.w));

        ulonglong2 wA = Wp[cin * 4 + 0];   // k-pairs 0,1
        ulonglong2 wB = Wp[cin * 4 + 1];   // k-pairs 2,3
        ulonglong2 wC = Wp[cin * 4 + 2];   // k-pairs 4,5
        ulonglong2 wD = Wp[cin * 4 + 3];   // k-pairs 6,7
#pragma unroll
        for (int mi = 0; mi < MP; ++mi) {
            asm("fma.rn.f32x2 %0, %1, %2, %0;" : "+l"(acc[mi][0]) : "l"(xv[mi]), "l"(wA.x));
            asm("fma.rn.f32x2 %0, %1, %2, %0;" : "+l"(acc[mi][1]) : "l"(xv[mi]), "l"(wA.y));
            asm("fma.rn.f32x2 %0, %1, %2, %0;" : "+l"(acc[mi][2]) : "l"(xv[mi]), "l"(wB.x));
            asm("fma.rn.f32x2 %0, %1, %2, %0;" : "+l"(acc[mi][3]) : "l"(xv[mi]), "l"(wB.y));
            asm("fma.rn.f32x2 %0, %1, %2, %0;" : "+l"(acc[mi][4]) : "l"(xv[mi]), "l"(wC.x));
            asm("fma.rn.f32x2 %0, %1, %2, %0;" : "+l"(acc[mi][5]) : "l"(xv[mi]), "l"(wC.y));
            asm("fma.rn.f32x2 %0, %1, %2, %0;" : "+l"(acc[mi][6]) : "l"(xv[mi]), "l"(wD.x));
            asm("fma.rn.f32x2 %0, %1, %2, %0;" : "+l"(acc[mi][7]) : "l"(xv[mi]), "l"(wD.y));
        }
    }

    // Store: column m+mi is 16 consecutive floats (k-pairs already k-ordered).
    // Thread's 4 columns are contiguous -> 16 fully coalesced STG.128.
    float* za = g_zbuf + (((size_t)half * B_SZ + b) * L_IN + m) * KW;
#pragma unroll
    for (int mi = 0; mi < MP; ++mi) {
        float f[KW];
#pragma unroll
        for (int j = 0; j < 8; ++j)
            asm("mov.b64 {%0, %1}, %2;" : "=f"(f[2*j]), "=f"(f[2*j+1]) : "l"(acc[mi][j]));
#pragma unroll
        for (int j = 0; j < 4; ++j)
            ((float4*)(za + mi * KW))[j] =
                make_float4(f[4*j], f[4*j+1], f[4*j+2], f[4*j+3]);
    }
}

// ---------------------------------------------------------------------------
// Kernel 2: one thread per m-column (m in [0, 3998]) produces 8 outputs:
//   y[b, 8m+p] = sum_halves ( z[m+1, p] + z[m, p+8] ),  p = 0..7
// Every z byte read exactly once, coalesced LDG/STG.128.
// ---------------------------------------------------------------------------
extern "C" __global__ void __launch_bounds__(128)
combine_kernel(float* __restrict__ out)
{
    const int mcol = blockIdx.x * 128 + threadIdx.x;
    const int b    = blockIdx.y;
    if (mcol > L_IN - 2) return;                       // m <= 3998

    const float4* z0 = (const float4*)(g_zbuf + ((size_t)b * L_IN) * KW);
    const float4* z1 = (const float4*)(g_zbuf + (((size_t)B_SZ + b) * L_IN) * KW);

    float4 a0 = z0[(mcol + 1) * 4 + 0];
    float4 a1 = z0[(mcol + 1) * 4 + 1];
    float4 b0 = z0[mcol * 4 + 2];
    float4 b1 = z0[mcol * 4 + 3];
    float4 c0 = z1[(mcol + 1) * 4 + 0];
    float4 c1 = z1[(mcol + 1) * 4 + 1];
    float4 d0 = z1[mcol * 4 + 2];
    float4 d1 = z1[mcol * 4 + 3];

    float4 o0 = make_float4((a0.x + b0.x) + (c0.x + d0.x),
                            (a0.y + b0.y) + (c0.y + d0.y),
                            (a0.z + b0.z) + (c0.z + d0.z),
                            (a0.w + b0.w) + (c0.w + d0.w));
    float4 o1 = make_float4((a1.x + b1.x) + (c1.x + d1.x),
                            (a1.y + b1.y) + (c1.y + d1.y),
                            (a1.z + b1.z) + (c1.z + d1.z),
                            (a1.w + b1.w) + (c1.w + d1.w));

    float4* op = (float4*)(out + (size_t)b * L_OUT + mcol * 8);
    op[0] = o0;
    op[1] = o1;
}

// ---------------------------------------------------------------------------
extern "C" void kernel_launch(void* const* d_in, const int* in_sizes, int n_in,
                              void* d_out, int out_size)
{
    const float* x    = (const float*)d_in[0];   // (16, 512, 4000) f32
    const float* t60s = (const float*)d_in[1];   // (8,)            f32
    const float* kw   = (const float*)d_in[2];   // (41, 512, 1, 16) f32
    float*       out  = (float*)d_out;           // (16, 1, 31992)  f32

    dim3 g1(4, B_SZ, CSPLIT);    // 4 m-tiles of 1024 columns, 16 samples, 2 halves
    zgemm_kernel<<<g1, 256>>>(x, t60s, kw);

    dim3 g2((L_IN - 1 + 127) / 128, B_SZ);       // 3999 m-columns per sample
    combine_kernel<<<g2, 128>>>(out);
}

// round 7
// speedup vs baseline: 1.4535x; 1.4535x over previous
#include <cuda_runtime.h>
#include <cuda_bf16.h>
#include <cstdint>

// Problem constants
#define B_SZ   16
#define CIN    512
#define L_IN   4000
#define KW     16
#define L_OUT  31992            // (4000-1)*8 - 16 + 16 = 3999*8
#define CSPLIT 2
#define CHALF  (CIN / CSPLIT)   // 256
#define MP     2                // m-values per thread

// Split-z scratch, pre-shifted for elementwise combine:
//   zA [half][b][m][p] = z[half][b][m  ][p+8]   (back half of column m)
//   zBs[half][b][m][p] = z[half][b][m+1][p  ]   (front half, shifted left 1)
// Then y[b][8m+p] = sum_half( zA[half][b][m][p] + zBs[half][b][m][p] ).
__device__ float g_zA [CSPLIT * B_SZ * L_IN * 8];   // 4.1 MB
__device__ float g_zBs[CSPLIT * B_SZ * L_IN * 8];   // 4.1 MB

// ---------------------------------------------------------------------------
// Kernel 1: per-sample skinny GEMM  z = x^T @ W_b, f32x2 packed over K-PAIRS.
// W in natural layout in smem (8 KB): per cin a thread does 4 broadcast
// LDS.128 + 1 LDG.64 (2 m-values of x) + 16 FFMA2.
// Grid: (8 m-tiles of 512, 16 batch, 2 cin-halves) = 256 blocks x 256 thr.
// __launch_bounds__(256,2): regs<=128 -> 2 blocks/SM -> 4 warps/SMSP.
// ---------------------------------------------------------------------------
extern "C" __global__ void __launch_bounds__(256, 2)
zgemm_kernel(const float* __restrict__ x,
             const float* __restrict__ t60s,
             const float* __restrict__ kw)
{
    __shared__ __align__(16) float Wsm[CHALF * KW];   // natural layout, 16 KB

    const int b    = blockIdx.y;
    const int half = blockIdx.z;
    // idx = round(t60*100) - 10, tiled so b>=8 reuses t60s[b-8]
    const int idxb = (int)rintf(t60s[b & 7] * 100.0f) - 10;
    const float4* wsrc = (const float4*)(kw + (size_t)idxb * (CIN * KW)
                                            + half * (CHALF * KW));
    float4* wdst = (float4*)Wsm;
    for (int i = threadIdx.x; i < CHALF * KW / 4; i += 256)
        wdst[i] = wsrc[i];
    __syncthreads();

    const int m = blockIdx.x * (256 * MP) + threadIdx.x * MP;
    if (m >= L_IN) return;   // last-tile guard (after the only __syncthreads)

    const float* xp = x + (size_t)b * CIN * L_IN + (size_t)half * CHALF * L_IN + m;
    const ulonglong2* Wp = (const ulonglong2*)Wsm;    // 4 x LDS.128 per cin row

    unsigned long long acc[MP][8];                    // [m][k-pair] {k_lo,k_hi}
#pragma unroll
    for (int mi = 0; mi < MP; ++mi)
#pragma unroll
        for (int j = 0; j < 8; ++j) acc[mi][j] = 0ULL;

#pragma unroll 8
    for (int cin = 0; cin < CHALF; ++cin) {
        float2 xq = *(const float2*)(xp + (size_t)cin * L_IN);   // m, m+1
        unsigned long long xv[MP];
        asm("mov.b64 %0, {%1, %1};" : "=l"(xv[0]) : "f"(xq.x));
        asm("mov.b64 %0, {%1, %1};" : "=l"(xv[1]) : "f"(xq.y));

        ulonglong2 wA = Wp[cin * 4 + 0];   // k-pairs 0,1
        ulonglong2 wB = Wp[cin * 4 + 1];   // k-pairs 2,3
        ulonglong2 wC = Wp[cin * 4 + 2];   // k-pairs 4,5
        ulonglong2 wD = Wp[cin * 4 + 3];   // k-pairs 6,7
#pragma unroll
        for (int mi = 0; mi < MP; ++mi) {
            asm("fma.rn.f32x2 %0, %1, %2, %0;" : "+l"(acc[mi][0]) : "l"(xv[mi]), "l"(wA.x));
            asm("fma.rn.f32x2 %0, %1, %2, %0;" : "+l"(acc[mi][1]) : "l"(xv[mi]), "l"(wA.y));
            asm("fma.rn.f32x2 %0, %1, %2, %0;" : "+l"(acc[mi][2]) : "l"(xv[mi]), "l"(wB.x));
            asm("fma.rn.f32x2 %0, %1, %2, %0;" : "+l"(acc[mi][3]) : "l"(xv[mi]), "l"(wB.y));
            asm("fma.rn.f32x2 %0, %1, %2, %0;" : "+l"(acc[mi][4]) : "l"(xv[mi]), "l"(wC.x));
            asm("fma.rn.f32x2 %0, %1, %2, %0;" : "+l"(acc[mi][5]) : "l"(xv[mi]), "l"(wC.y));
            asm("fma.rn.f32x2 %0, %1, %2, %0;" : "+l"(acc[mi][6]) : "l"(xv[mi]), "l"(wD.x));
            asm("fma.rn.f32x2 %0, %1, %2, %0;" : "+l"(acc[mi][7]) : "l"(xv[mi]), "l"(wD.y));
        }
    }

    // Store split-z: back half -> zA[m], front half -> zBs[m-1] (shifted).
    const size_t colbase = (((size_t)half * B_SZ + b) * L_IN + m) * 8;
    float* zA  = g_zA  + colbase;
    float* zBs = g_zBs + colbase - 8;      // column m-1 slot (guarded for m==0)
#pragma unroll
    for (int mi = 0; mi < MP; ++mi) {
        float f[KW];
#pragma unroll
        for (int j = 0; j < 8; ++j)
            asm("mov.b64 {%0, %1}, %2;" : "=f"(f[2*j]), "=f"(f[2*j+1]) : "l"(acc[mi][j]));

        ((float4*)(zA + mi * 8))[0] = make_float4(f[ 8], f[ 9], f[10], f[11]);
        ((float4*)(zA + mi * 8))[1] = make_float4(f[12], f[13], f[14], f[15]);
        if (m + mi > 0) {
            ((float4*)(zBs + mi * 8))[0] = make_float4(f[0], f[1], f[2], f[3]);
            ((float4*)(zBs + mi * 8))[1] = make_float4(f[4], f[5], f[6], f[7]);
        }
    }
}

// ---------------------------------------------------------------------------
// Kernel 2: pure elementwise float4 add (fully coalesced, zero index math):
//   out4[b][i] = zA0[i] + zBs0[i] + zA1[i] + zBs1[i],  i in [0, 7998)
// ---------------------------------------------------------------------------
extern "C" __global__ void __launch_bounds__(256)
combine_kernel(float* __restrict__ out)
{
    const int i = blockIdx.x * 256 + threadIdx.x;
    const int b = blockIdx.y;
    if (i >= (L_OUT / 4)) return;                      // 7998 float4 per sample

    const float4* zA0 = (const float4*)g_zA  + (size_t)b * L_IN * 2;
    const float4* zB0 = (const float4*)g_zBs + (size_t)b * L_IN * 2;
    const float4* zA1 = (const float4*)g_zA  + ((size_t)B_SZ + b) * L_IN * 2;
    const float4* zB1 = (const float4*)g_zBs + ((size_t)B_SZ + b) * L_IN * 2;

    float4 a = zA0[i], p = zB0[i], c = zA1[i], q = zB1[i];
    float4 o = make_float4((a.x + p.x) + (c.x + q.x),
                           (a.y + p.y) + (c.y + q.y),
                           (a.z + p.z) + (c.z + q.z),
                           (a.w + p.w) + (c.w + q.w));
    ((float4*)(out + (size_t)b * L_OUT))[i] = o;
}

// ---------------------------------------------------------------------------
extern "C" void kernel_launch(void* const* d_in, const int* in_sizes, int n_in,
                              void* d_out, int out_size)
{
    const float* x    = (const float*)d_in[0];   // (16, 512, 4000) f32
    const float* t60s = (const float*)d_in[1];   // (8,)            f32
    const float* kw   = (const float*)d_in[2];   // (41, 512, 1, 16) f32
    float*       out  = (float*)d_out;           // (16, 1, 31992)  f32

    dim3 g1(8, B_SZ, CSPLIT);    // 8 m-tiles of 512 columns, 16 samples, 2 halves
    zgemm_kernel<<<g1, 256>>>(x, t60s, kw);

    dim3 g2((L_OUT / 4 + 255) / 256, B_SZ);      // 7998 float4 per sample
    combine_kernel<<<g2, 256>>>(out);
}